// round 11
// baseline (speedup 1.0000x reference)
#include <cuda_runtime.h>

// x: [N=256, 3, 3, num=256, F=128] fp32, contiguous.
// out: [N, 3, 3, G=128, F=128] fp32.
// Winner per pair = larger rotation angle acos(clip((tr-1)/2,-1,1));
// acos decreasing => winner = smaller clamp(tr,-1,3); ties -> candidate 0.
//
// R11: 256-bit memory ops (sm_103a ld.global.nc.v8.f32 / st.global.v8.f32).
// B300 addr->LTS hash ignores bit 7, so both 128B lines of one 256B access
// hit the SAME L2 slice -> paired same-row bursts at the HBM controller ->
// higher page-hit rate, less read/write turnaround (the measured ~16% DRAM
// idle). Phasing from R9 (best DRAM%): diag->mask->retire, off-diags in
// batches of 2 positions to keep liveness under the 64-reg occ-4 budget.

#define F8_   16                      // 128 floats = 16 chunks of 8
#define TOT   (256 * 128 * F8_)       // 524,288 threads

// float strides
#define XSD   32768                   // per (d1*3+d2) step: 256*128
#define XSM   128                     // per num step
#define XSN   294912                  // 9*32768
#define OSD   16384                   // 128*128
#define OSG   128
#define OSN   147456                  // 9*16384

__device__ __forceinline__ float clamp_tr(float t) {
    return fminf(fmaxf(t, -1.0f), 3.0f);
}

// 256-bit streaming load (read-only path)
__device__ __forceinline__ void ldg8(const float* p, float* r) {
    asm volatile("ld.global.nc.v8.f32 {%0,%1,%2,%3,%4,%5,%6,%7}, [%8];"
        : "=f"(r[0]), "=f"(r[1]), "=f"(r[2]), "=f"(r[3]),
          "=f"(r[4]), "=f"(r[5]), "=f"(r[6]), "=f"(r[7])
        : "l"(p));
}

// 256-bit store
__device__ __forceinline__ void stg8(float* p, const float* r) {
    asm volatile("st.global.v8.f32 [%0], {%1,%2,%3,%4,%5,%6,%7,%8};"
        :: "l"(p),
           "f"(r[0]), "f"(r[1]), "f"(r[2]), "f"(r[3]),
           "f"(r[4]), "f"(r[5]), "f"(r[6]), "f"(r[7])
        : "memory");
}

// select winner per component and store one output position
__device__ __forceinline__ void sel_store(float* p, const bool* s,
                                          const float* a, const float* b) {
    float r[8];
#pragma unroll
    for (int j = 0; j < 8; j++) r[j] = s[j] ? b[j] : a[j];
    stg8(p, r);
}

__global__ __launch_bounds__(256, 4)
void Pooling_5866925326754_kernel(const float* __restrict__ xv,
                                  float* __restrict__ ov) {
    int idx = blockIdx.x * blockDim.x + threadIdx.x;

    int f8 = idx & (F8_ - 1);
    int g  = (idx >> 4) & 127;
    int n  = idx >> 11;

    const float* pa = xv + n * XSN + (2 * g) * XSM + f8 * 8;
    const float* pb = pa + XSM;
    float*       po = ov + n * OSN + g * OSG + f8 * 8;

    // ---- phase 1: diagonals -> mask -> retire d = 0,4,8 ----
    float a0[8], a4[8], a8[8], b0[8], b4[8], b8[8];
    ldg8(pa + 0 * XSD, a0);
    ldg8(pa + 4 * XSD, a4);
    ldg8(pa + 8 * XSD, a8);
    ldg8(pb + 0 * XSD, b0);
    ldg8(pb + 4 * XSD, b4);
    ldg8(pb + 8 * XSD, b8);

    bool s[8];
#pragma unroll
    for (int j = 0; j < 8; j++) {
        // candidate 1 wins only on strictly smaller clamped trace
        s[j] = clamp_tr(b0[j] + b4[j] + b8[j]) <
               clamp_tr(a0[j] + a4[j] + a8[j]);
    }

    sel_store(po + 0 * OSD, s, a0, b0);
    sel_store(po + 4 * OSD, s, a4, b4);
    sel_store(po + 8 * OSD, s, a8, b8);

    // ---- phase 2: off-diagonals in batches of 2 positions ----
    {
        float a1[8], a2[8], b1[8], b2[8];
        ldg8(pa + 1 * XSD, a1);
        ldg8(pa + 2 * XSD, a2);
        ldg8(pb + 1 * XSD, b1);
        ldg8(pb + 2 * XSD, b2);
        sel_store(po + 1 * OSD, s, a1, b1);
        sel_store(po + 2 * OSD, s, a2, b2);
    }
    {
        float a3[8], a5[8], b3[8], b5[8];
        ldg8(pa + 3 * XSD, a3);
        ldg8(pa + 5 * XSD, a5);
        ldg8(pb + 3 * XSD, b3);
        ldg8(pb + 5 * XSD, b5);
        sel_store(po + 3 * OSD, s, a3, b3);
        sel_store(po + 5 * OSD, s, a5, b5);
    }
    {
        float a6[8], a7[8], b6[8], b7[8];
        ldg8(pa + 6 * XSD, a6);
        ldg8(pa + 7 * XSD, a7);
        ldg8(pb + 6 * XSD, b6);
        ldg8(pb + 7 * XSD, b7);
        sel_store(po + 6 * OSD, s, a6, b6);
        sel_store(po + 7 * OSD, s, a7, b7);
    }
}

extern "C" void kernel_launch(void* const* d_in, const int* in_sizes, int n_in,
                              void* d_out, int out_size) {
    const float* x = (const float*)d_in[0];
    float* out = (float*)d_out;
    (void)in_sizes; (void)n_in; (void)out_size;
    Pooling_5866925326754_kernel<<<TOT / 256, 256>>>(x, out);
}

// round 12
// speedup vs baseline: 1.0385x; 1.0385x over previous
#include <cuda_runtime.h>

// x: [N=256, 3, 3, num=256, F=128] fp32, contiguous.
// out: [N, 3, 3, G=128, F=128] fp32.
// Winner per pair = larger rotation angle acos(clip((tr-1)/2,-1,1));
// acos decreasing => winner = smaller clamp(tr,-1,3); ties -> candidate 0.
//
// R12: R9 body (best DRAM%: __ldcs/__stcs, diag-first phasing, ~38 regs)
// with BLK=512 / launch_bounds(512,3) (48 warps/SM, same as R9's occ-6).
// Rationale: all SM-side levers plateau at DRAM ~84%; residual idle is HBM
// page-miss/turnaround across the 27 per-CTA address streams. Doubling CTA
// size halves distinct stream heads chip-wide and doubles each contiguous
// segment (16KB reads / 8KB writes per d per CTA) -> fewer row activations
// per byte. v8/persistent/write-back variants all reverted (regressed).

#define N_    256
#define G_    128
#define F4_   32                      // 128 floats = 32 float4
#define TOT   (N_ * G_ * F4_)         // 1,048,576 threads
#define BLK   512

// strides in float4 units
#define XSD   8192                    // per (d1*3+d2) step
#define XSM   32                      // per num step
#define XSN   73728                   // 9*8192
#define OSD   4096
#define OSG   32
#define OSN   36864                   // 9*4096

__device__ __forceinline__ float clamp_tr(float t) {
    return fminf(fmaxf(t, -1.0f), 3.0f);
}

__device__ __forceinline__ float4 sel4(bool sx, bool sy, bool sz, bool sw,
                                       const float4& a, const float4& b) {
    float4 r;
    r.x = sx ? b.x : a.x;
    r.y = sy ? b.y : a.y;
    r.z = sz ? b.z : a.z;
    r.w = sw ? b.w : a.w;
    return r;
}

__global__ __launch_bounds__(BLK, 3)
void Pooling_5866925326754_kernel(const float4* __restrict__ xv,
                                  float4* __restrict__ ov) {
    int idx = blockIdx.x * BLK + threadIdx.x;

    int f4 = idx & (F4_ - 1);
    int g  = (idx >> 5) & (G_ - 1);
    int n  = idx >> 12;

    const float4* pa = xv + n * XSN + (2 * g) * XSM + f4;
    const float4* pb = pa + XSM;
    float4*       po = ov + n * OSN + g * OSG + f4;

    // ---- phase 1: diagonals (6 loads) -> mask -> retire d=0,4,8 ----
    float4 a0 = __ldcs(pa + 0 * XSD);
    float4 a4 = __ldcs(pa + 4 * XSD);
    float4 a8 = __ldcs(pa + 8 * XSD);
    float4 b0 = __ldcs(pb + 0 * XSD);
    float4 b4 = __ldcs(pb + 4 * XSD);
    float4 b8 = __ldcs(pb + 8 * XSD);

    // candidate 1 wins only on strictly smaller clamped trace
    bool sx = clamp_tr(b0.x + b4.x + b8.x) < clamp_tr(a0.x + a4.x + a8.x);
    bool sy = clamp_tr(b0.y + b4.y + b8.y) < clamp_tr(a0.y + a4.y + a8.y);
    bool sz = clamp_tr(b0.z + b4.z + b8.z) < clamp_tr(a0.z + a4.z + a8.z);
    bool sw = clamp_tr(b0.w + b4.w + b8.w) < clamp_tr(a0.w + a4.w + a8.w);

    __stcs(po + 0 * OSD, sel4(sx, sy, sz, sw, a0, b0));
    __stcs(po + 4 * OSD, sel4(sx, sy, sz, sw, a4, b4));
    __stcs(po + 8 * OSD, sel4(sx, sy, sz, sw, a8, b8));

    // ---- phase 2a: off-diagonals d = 1,2,3 (6 loads, 3 stores) ----
    {
        float4 a1 = __ldcs(pa + 1 * XSD);
        float4 a2 = __ldcs(pa + 2 * XSD);
        float4 a3 = __ldcs(pa + 3 * XSD);
        float4 b1 = __ldcs(pb + 1 * XSD);
        float4 b2 = __ldcs(pb + 2 * XSD);
        float4 b3 = __ldcs(pb + 3 * XSD);
        __stcs(po + 1 * OSD, sel4(sx, sy, sz, sw, a1, b1));
        __stcs(po + 2 * OSD, sel4(sx, sy, sz, sw, a2, b2));
        __stcs(po + 3 * OSD, sel4(sx, sy, sz, sw, a3, b3));
    }

    // ---- phase 2b: off-diagonals d = 5,6,7 (6 loads, 3 stores) ----
    {
        float4 a5 = __ldcs(pa + 5 * XSD);
        float4 a6 = __ldcs(pa + 6 * XSD);
        float4 a7 = __ldcs(pa + 7 * XSD);
        float4 b5 = __ldcs(pb + 5 * XSD);
        float4 b6 = __ldcs(pb + 6 * XSD);
        float4 b7 = __ldcs(pb + 7 * XSD);
        __stcs(po + 5 * OSD, sel4(sx, sy, sz, sw, a5, b5));
        __stcs(po + 6 * OSD, sel4(sx, sy, sz, sw, a6, b6));
        __stcs(po + 7 * OSD, sel4(sx, sy, sz, sw, a7, b7));
    }
}

extern "C" void kernel_launch(void* const* d_in, const int* in_sizes, int n_in,
                              void* d_out, int out_size) {
    const float4* x = (const float4*)d_in[0];
    float4* out = (float4*)d_out;
    (void)in_sizes; (void)n_in; (void)out_size;
    Pooling_5866925326754_kernel<<<TOT / BLK, BLK>>>(x, out);
}